// round 2
// baseline (speedup 1.0000x reference)
#include <cuda_runtime.h>

// MoE router, fused: jitter -> fp32 GEMM (N=16384, D=4096, E=64) -> softmax
// -> top-8 (biased) -> L2-normalized weights -> bincount.
// fp32 math throughout (ranking must match JAX fp32 reference bit-closely).
// GEMM uses fma.rn.f32x2 (FFMA2) with k-pair packing: acc f32x2 holds
// (even-k, odd-k) partial sums; reduced at the end. 2x fp32 throughput.

#define N_TOK   16384
#define DIM     4096
#define NEXP    64
#define TOPK    8
#define MT      128           // tokens per block
#define KT      16            // K columns per pipeline tile
#define KP      (KT/2)        // k-pairs per tile = 8
#define THREADS 128
#define NTILES  (DIM / KT)    // 256
#define NBLK    (N_TOK / MT)  // 128

#define OFF_LOGITS 0
#define OFF_SCORES (N_TOK * NEXP)                       // 1048576
#define OFF_W      (2 * N_TOK * NEXP)                   // 2097152
#define OFF_IDX    (2 * N_TOK * NEXP + N_TOK * TOPK)    // 2228224
#define OFF_CNT    (2 * N_TOK * NEXP + 2 * N_TOK * TOPK)// 2359296

typedef unsigned long long u64;

__device__ __forceinline__ u64 ffma2(u64 a, u64 b, u64 c) {
    u64 d;
    asm("fma.rn.f32x2 %0, %1, %2, %3;" : "=l"(d) : "l"(a), "l"(b), "l"(c));
    return d;
}
__device__ __forceinline__ u64 pack2(float lo, float hi) {
    u64 d;
    asm("mov.b64 %0, {%1, %2};" : "=l"(d) : "f"(lo), "f"(hi));
    return d;
}
__device__ __forceinline__ void unpack2(u64 v, float& lo, float& hi) {
    asm("mov.b64 {%0, %1}, %2;" : "=f"(lo), "=f"(hi) : "l"(v));
}

// XOR swizzle on the token index of the x tile so that the 64B-strided
// a-loads in the mainloop hit distinct bank groups (2-phase minimum instead
// of 8-way conflicts). Pure XOR of bits[3:1] with bits[6:3]'s low 3 —
// bijective, preserves 16B pair adjacency/alignment (bit 0 untouched).
__device__ __forceinline__ int SWZ(int m) { return m ^ (2 * ((m >> 3) & 7)); }

struct SmemT {
    union {
        struct {
            u64 xs[2][KP][MT];    // packed (x[2kp], x[2kp+1]) per token, swizzled index
            u64 ws[2][KP][NEXP];  // packed (W[2kp][e], W[2kp+1][e])
        };
        float L[MT * 65];         // logits/scores tile, stride 65 (conflict-free rows)
    };
    float sbias[NEXP];
    float cnt[NEXP];
};

__global__ void zero_cnt_kernel(float* g) {
    g[threadIdx.x] = 0.0f;
}

__global__ void __launch_bounds__(THREADS, 1)
router_kernel(const float* __restrict__ x, const float* __restrict__ W,
              const float* __restrict__ sbias_g, const float* __restrict__ noise,
              float* __restrict__ out) {
    __shared__ SmemT sm;
    const int tid  = threadIdx.x;
    const int tok0 = blockIdx.x * MT;

    if (tid < NEXP) { sm.sbias[tid] = sbias_g[tid]; sm.cnt[tid] = 0.0f; }

    const int tr = tid & 15;   // token group: rows tr*8 .. tr*8+7
    const int ec = tid >> 4;   // expert group: cols ec*8 .. ec*8+7

    u64 acc[8][8];
#pragma unroll
    for (int i = 0; i < 8; ++i)
#pragma unroll
        for (int j = 0; j < 8; ++j) acc[i][j] = 0ull;

    const float* xrow = x     + (size_t)(tok0 + tid) * DIM;
    const float* nrow = noise + (size_t)(tok0 + tid) * DIM;

    float4 sx[4], sn[4], sw[2];

    // ---- prefetch tile 0 ----
#pragma unroll
    for (int j = 0; j < 4; ++j) {
        sx[j] = *(const float4*)(xrow + 4 * j);
        sn[j] = *(const float4*)(nrow + 4 * j);
    }
#pragma unroll
    for (int j = 0; j < 2; ++j) {
        int idx = tid + j * THREADS;        // 0..255
        int r = idx >> 4, c = (idx & 15) * 4;
        sw[j] = *(const float4*)(W + (size_t)r * NEXP + c);
    }
    // ---- store tile 0 into buffer 0 ----
    {
        const int ms = SWZ(tid);
#pragma unroll
        for (int j = 0; j < 4; ++j) {
            float v0 = sx[j].x * (0.99f + sn[j].x * 0.02f);
            float v1 = sx[j].y * (0.99f + sn[j].y * 0.02f);
            float v2 = sx[j].z * (0.99f + sn[j].z * 0.02f);
            float v3 = sx[j].w * (0.99f + sn[j].w * 0.02f);
            sm.xs[0][2 * j][ms]     = pack2(v0, v1);
            sm.xs[0][2 * j + 1][ms] = pack2(v2, v3);
        }
#pragma unroll
        for (int j = 0; j < 2; ++j) {
            int idx = tid + j * THREADS;
            int r = idx >> 4, c = (idx & 15) * 4, h = r & 1;
            float* base = (float*)&sm.ws[0][r >> 1][0];
            base[2 * (c + 0) + h] = sw[j].x;
            base[2 * (c + 1) + h] = sw[j].y;
            base[2 * (c + 2) + h] = sw[j].z;
            base[2 * (c + 3) + h] = sw[j].w;
        }
    }
    __syncthreads();

    // ---- main pipeline ----
#pragma unroll 1
    for (int t = 0; t < NTILES; ++t) {
        const int buf  = t & 1;
        const bool more = (t + 1 < NTILES);
        const int k0n = (t + 1) * KT;

        if (more) {  // issue prefetch LDGs; they land under the compute below
#pragma unroll
            for (int j = 0; j < 4; ++j) {
                sx[j] = *(const float4*)(xrow + k0n + 4 * j);
                sn[j] = *(const float4*)(nrow + k0n + 4 * j);
            }
#pragma unroll
            for (int j = 0; j < 2; ++j) {
                int idx = tid + j * THREADS;
                int r = idx >> 4, c = (idx & 15) * 4;
                sw[j] = *(const float4*)(W + (size_t)(k0n + r) * NEXP + c);
            }
        }

        // compute on smem[buf]
#pragma unroll
        for (int kp = 0; kp < KP; ++kp) {
            u64 a[8], b[8];
            const int q2 = 2 * (tr & 7);
#pragma unroll
            for (int i = 0; i < 4; ++i) {
                int mi = (tr * 8 + 2 * i) ^ q2;   // = SWZ(tr*8 + 2i), pure XOR (no carry!)
                ulonglong2 qv = *(const ulonglong2*)&sm.xs[buf][kp][mi];
                a[2 * i] = qv.x; a[2 * i + 1] = qv.y;
            }
#pragma unroll
            for (int j = 0; j < 4; ++j) {
                ulonglong2 qv = *(const ulonglong2*)&sm.ws[buf][kp][ec * 8 + 2 * j];
                b[2 * j] = qv.x; b[2 * j + 1] = qv.y;
            }
#pragma unroll
            for (int i = 0; i < 8; ++i)
#pragma unroll
                for (int j = 0; j < 8; ++j)
                    acc[i][j] = ffma2(a[i], b[j], acc[i][j]);
        }

        if (more) {  // store prefetched tile into the other buffer
            const int nb = buf ^ 1;
            const int ms = SWZ(tid);
#pragma unroll
            for (int j = 0; j < 4; ++j) {
                float v0 = sx[j].x * (0.99f + sn[j].x * 0.02f);
                float v1 = sx[j].y * (0.99f + sn[j].y * 0.02f);
                float v2 = sx[j].z * (0.99f + sn[j].z * 0.02f);
                float v3 = sx[j].w * (0.99f + sn[j].w * 0.02f);
                sm.xs[nb][2 * j][ms]     = pack2(v0, v1);
                sm.xs[nb][2 * j + 1][ms] = pack2(v2, v3);
            }
#pragma unroll
            for (int j = 0; j < 2; ++j) {
                int idx = tid + j * THREADS;
                int r = idx >> 4, c = (idx & 15) * 4, h = r & 1;
                float* base = (float*)&sm.ws[nb][r >> 1][0];
                base[2 * (c + 0) + h] = sw[j].x;
                base[2 * (c + 1) + h] = sw[j].y;
                base[2 * (c + 2) + h] = sw[j].z;
                base[2 * (c + 3) + h] = sw[j].w;
            }
        }
        __syncthreads();
    }

    // ---- epilogue ----
    // reduce k-pair halves, stage logits in smem (stride 65)
    float* L = sm.L;
#pragma unroll
    for (int i = 0; i < 8; ++i)
#pragma unroll
        for (int j = 0; j < 8; ++j) {
            float lo, hi;
            unpack2(acc[i][j], lo, hi);
            L[(tr * 8 + i) * 65 + (ec * 8 + j)] = lo + hi;
        }
    __syncthreads();

    // coalesced logits write
    float* gL = out + OFF_LOGITS + (size_t)tok0 * NEXP;
    for (int idx = tid; idx < MT * NEXP; idx += THREADS)
        gL[idx] = L[(idx >> 6) * 65 + (idx & 63)];
    __syncthreads();

    // per-token softmax in place (thread tid owns token tid)
    {
        float* row = L + tid * 65;
        float mx = row[0];
#pragma unroll 8
        for (int e = 1; e < NEXP; ++e) mx = fmaxf(mx, row[e]);
        float s = 0.0f;
#pragma unroll 8
        for (int e = 0; e < NEXP; ++e) s += expf(row[e] - mx);
        float inv = 1.0f / s;
#pragma unroll 8
        for (int e = 0; e < NEXP; ++e) row[e] = expf(row[e] - mx) * inv;
    }
    __syncthreads();

    // coalesced scores write
    float* gS = out + OFF_SCORES + (size_t)tok0 * NEXP;
    for (int idx = tid; idx < MT * NEXP; idx += THREADS)
        gS[idx] = L[(idx >> 6) * 65 + (idx & 63)];

    // top-k (biased ranking; strict > keeps the lowest index on ties,
    // matching jax.lax.top_k), weights from unbiased scores, L2 norm.
    {
        const float* row = L + tid * 65;
        float w[TOPK];
        int   ix[TOPK];
        u64 mask = 0ull;
#pragma unroll
        for (int k = 0; k < TOPK; ++k) {
            float best = -1e30f;
            int bi = 0;
            for (int e = 0; e < NEXP; ++e) {
                if (!((mask >> e) & 1ull)) {
                    float v = row[e] + sm.sbias[e];
                    if (v > best) { best = v; bi = e; }
                }
            }
            mask |= 1ull << bi;
            ix[k] = bi;
            w[k] = row[bi];
        }
        float ss = 0.0f;
#pragma unroll
        for (int k = 0; k < TOPK; ++k) ss += w[k] * w[k];
        float inv = 1.0f / sqrtf(ss);

        const int tok = tok0 + tid;
        float* gW = out + OFF_W   + (size_t)tok * TOPK;
        float* gI = out + OFF_IDX + (size_t)tok * TOPK;
#pragma unroll
        for (int k = 0; k < TOPK; ++k) {
            gW[k] = w[k] * inv;
            gI[k] = (float)ix[k];
            atomicAdd(&sm.cnt[ix[k]], 1.0f);
        }
    }
    __syncthreads();

    // flush per-block expert counts (integer-valued floats: exact, order-free)
    if (tid < NEXP) {
        float c = sm.cnt[tid];
        if (c != 0.0f) atomicAdd(out + OFF_CNT + tid, c);
    }
}

extern "C" void kernel_launch(void* const* d_in, const int* in_sizes, int n_in,
                              void* d_out, int out_size) {
    const float* x     = (const float*)d_in[0];
    const float* W     = (const float*)d_in[1];
    const float* sbias = (const float*)d_in[2];
    const float* noise = (const float*)d_in[3];
    float* out = (float*)d_out;

    zero_cnt_kernel<<<1, NEXP>>>(out + OFF_CNT);
    router_kernel<<<NBLK, THREADS>>>(x, W, sbias, noise, out);
}

// round 5
// speedup vs baseline: 1.0136x; 1.0136x over previous
#include <cuda_runtime.h>
#include <cstdint>

// MoE router: jitter -> GEMM (16384x4096 @ 4096x64) -> softmax -> biased top-8
// -> L2-norm weights -> bincount.  GEMM on tensor cores via legacy
// mma.sync.m16n8k8.tf32 (sm_103 base target), 3xTF32 split.
// Near-tie tokens (min adjacent top-9 gap < THRESH) get their 12 candidate
// logits recomputed in exact fp32 by a repair kernel -> zero top-k flips.

#define N_TOK   16384
#define DIM     4096
#define NEXP    64
#define TOPK    8
#define NCAND   12
#define MT      128
#define KC      32              // K per chunk (4 k8-steps)
#define NCHUNK  (DIM / KC)      // 128
#define THREADS 256
#define NBLK    (N_TOK / MT)    // 128
#define NK8     (DIM / 8)       // 512
#define THRESH  2e-5f

#define OFF_LOGITS 0
#define OFF_SCORES (N_TOK * NEXP)
#define OFF_W      (2 * N_TOK * NEXP)
#define OFF_IDX    (2 * N_TOK * NEXP + N_TOK * TOPK)
#define OFF_CNT    (2 * N_TOK * NEXP + 2 * N_TOK * TOPK)

#define AHI(b) ((b) * 16384)
#define ALO(b) (32768 + (b) * 16384)
#define BHI(b) (65536 + (b) * 8192)
#define BLO(b) (81920 + (b) * 8192)
#define SMEM_BYTES 98304

typedef unsigned long long u64;

__device__ u64 g_Bh[NK8 * NEXP * 4];
__device__ u64 g_Bl[NK8 * NEXP * 4];
__device__ float g_WT[NEXP * DIM];      // W transposed fp32: [e][k]
__device__ int g_nflag;
__device__ int g_list[N_TOK];
__device__ int g_cand[N_TOK * NCAND];

__device__ __forceinline__ uint32_t to_tf32(float v) {
    uint32_t r;
    asm("cvt.rna.tf32.f32 %0, %1;" : "=r"(r) : "f"(v));
    return r;
}

__device__ __forceinline__ void mma_tf32(float* c,
                                         uint32_t a0, uint32_t a1, uint32_t a2, uint32_t a3,
                                         uint32_t b0, uint32_t b1) {
    asm volatile(
        "mma.sync.aligned.m16n8k8.row.col.f32.tf32.tf32.f32 "
        "{%0,%1,%2,%3}, {%4,%5,%6,%7}, {%8,%9}, {%0,%1,%2,%3};"
        : "+f"(c[0]), "+f"(c[1]), "+f"(c[2]), "+f"(c[3])
        : "r"(a0), "r"(a1), "r"(a2), "r"(a3), "r"(b0), "r"(b1));
}

__device__ __forceinline__ uint32_t aoff(int tok, int c2) {
    return (uint32_t)(tok * 32 + ((c2 ^ (tok & 3) ^ ((tok >> 2) & 3)) << 3));
}

__global__ void zero_cnt_kernel(float* g) {
    g[threadIdx.x] = 0.0f;
    if (threadIdx.x == 0) g_nflag = 0;
}

__global__ void prep_W_kernel(const float* __restrict__ W) {
    int p = blockIdx.x * 256 + threadIdx.x;
    int e   = p & 63;
    int tig = (p >> 6) & 3;
    int k8  = p >> 8;
    int k = k8 * 8 + tig;
    float w0 = W[(size_t)k * NEXP + e];
    float w1 = W[(size_t)(k + 4) * NEXP + e];
    uint32_t h0 = to_tf32(w0), h1 = to_tf32(w1);
    uint32_t l0 = to_tf32(w0 - __uint_as_float(h0));
    uint32_t l1 = to_tf32(w1 - __uint_as_float(h1));
    size_t idx = (size_t)k8 * 256 + e * 4 + tig;
    g_Bh[idx] = ((u64)h1 << 32) | h0;
    g_Bl[idx] = ((u64)l1 << 32) | l0;
    g_WT[(size_t)e * DIM + k]     = w0;
    g_WT[(size_t)e * DIM + k + 4] = w1;
}

__global__ void __launch_bounds__(THREADS, 1)
router_kernel(const float* __restrict__ x, const float* __restrict__ sbias_g,
              const float* __restrict__ noise, float* __restrict__ out) {
    extern __shared__ char db[];
    __shared__ float s_bias[NEXP];

    const int tid  = threadIdx.x;
    const int wid  = tid >> 5;
    const int lane = tid & 31;
    const int g    = lane >> 2;
    const int tig  = lane & 3;
    const int set  = wid >> 2;
    const int wTok = (wid & 3) * 32;
    const int tok0 = blockIdx.x * MT;

    if (tid < NEXP) s_bias[tid] = sbias_g[tid];

    const int t_tok  = tid & 127;
    const int t_half = tid >> 7;
    const float* xg = x     + (size_t)(tok0 + t_tok) * DIM + t_half * 16;
    const float* ng = noise + (size_t)(tok0 + t_tok) * DIM + t_half * 16;
    const uint4* pBh = (const uint4*)g_Bh;
    const uint4* pBl = (const uint4*)g_Bl;

    float acc[2][8][4];
#pragma unroll
    for (int mt = 0; mt < 2; ++mt)
#pragma unroll
        for (int j = 0; j < 8; ++j)
#pragma unroll
            for (int q = 0; q < 4; ++q) acc[mt][j][q] = 0.0f;

    float4 rx[4], rn[4];
    uint4  rbh[2], rbl[2];

#pragma unroll
    for (int j = 0; j < 4; ++j) {
        rx[j] = *(const float4*)(xg + 4 * j);
        rn[j] = *(const float4*)(ng + 4 * j);
    }
    rbh[0] = pBh[tid];       rbh[1] = pBh[256 + tid];
    rbl[0] = pBl[tid];       rbl[1] = pBl[256 + tid];

#define STORE_CHUNK(BUF) do {                                                   \
        uint32_t hh[16], ll[16];                                                \
        _Pragma("unroll")                                                       \
        for (int j = 0; j < 4; ++j) {                                           \
            float vx0 = rx[j].x * (0.99f + rn[j].x * 0.02f);                    \
            float vx1 = rx[j].y * (0.99f + rn[j].y * 0.02f);                    \
            float vx2 = rx[j].z * (0.99f + rn[j].z * 0.02f);                    \
            float vx3 = rx[j].w * (0.99f + rn[j].w * 0.02f);                    \
            hh[4*j+0] = to_tf32(vx0); ll[4*j+0] = to_tf32(vx0 - __uint_as_float(hh[4*j+0])); \
            hh[4*j+1] = to_tf32(vx1); ll[4*j+1] = to_tf32(vx1 - __uint_as_float(hh[4*j+1])); \
            hh[4*j+2] = to_tf32(vx2); ll[4*j+2] = to_tf32(vx2 - __uint_as_float(hh[4*j+2])); \
            hh[4*j+3] = to_tf32(vx3); ll[4*j+3] = to_tf32(vx3 - __uint_as_float(hh[4*j+3])); \
        }                                                                       \
        _Pragma("unroll")                                                       \
        for (int jj = 0; jj < 2; ++jj)                                          \
            _Pragma("unroll")                                                   \
            for (int c2 = 0; c2 < 4; ++c2) {                                    \
                uint32_t o = (uint32_t)((2 * t_half + jj) * 4096) + aoff(t_tok, c2); \
                *(uint2*)(db + AHI(BUF) + o) = make_uint2(hh[jj*8+c2], hh[jj*8+c2+4]); \
                *(uint2*)(db + ALO(BUF) + o) = make_uint2(ll[jj*8+c2], ll[jj*8+c2+4]); \
            }                                                                   \
        ((uint4*)(db + BHI(BUF)))[tid]       = rbh[0];                          \
        ((uint4*)(db + BHI(BUF)))[256 + tid] = rbh[1];                          \
        ((uint4*)(db + BLO(BUF)))[tid]       = rbl[0];                          \
        ((uint4*)(db + BLO(BUF)))[256 + tid] = rbl[1];                          \
    } while (0)

    STORE_CHUNK(0);
    __syncthreads();

#pragma unroll 1
    for (int c = 0; c < NCHUNK; ++c) {
        const int buf = c & 1;
        const bool more = (c + 1 < NCHUNK);

        if (more) {
            const int cb = (c + 1) * KC;
#pragma unroll
            for (int j = 0; j < 4; ++j) {
                rx[j] = *(const float4*)(xg + cb + 4 * j);
                rn[j] = *(const float4*)(ng + cb + 4 * j);
            }
            const int bb = (c + 1) * 512;
            rbh[0] = pBh[bb + tid];       rbh[1] = pBh[bb + 256 + tid];
            rbl[0] = pBl[bb + tid];       rbl[1] = pBl[bb + 256 + tid];
        }

#pragma unroll
        for (int jj = 0; jj < 2; ++jj) {
            const int k8r = set * 2 + jj;
            const char* Ah = db + AHI(buf) + k8r * 4096;
            const char* Al = db + ALO(buf) + k8r * 4096;
            const char* Bh = db + BHI(buf) + k8r * 2048;
            const char* Bl = db + BLO(buf) + k8r * 2048;

            uint2 af[2][2], bf[8];
#pragma unroll
            for (int mt = 0; mt < 2; ++mt) {
                int tA = wTok + mt * 16 + g;
                af[mt][0] = *(const uint2*)(Ah + aoff(tA, tig));
                af[mt][1] = *(const uint2*)(Ah + aoff(tA + 8, tig));
            }
#pragma unroll
            for (int j = 0; j < 8; ++j)
                bf[j] = *(const uint2*)(Bh + (j * 8 + g) * 32 + tig * 8);
#pragma unroll
            for (int mt = 0; mt < 2; ++mt)
#pragma unroll
                for (int j = 0; j < 8; ++j)
                    mma_tf32(acc[mt][j], af[mt][0].x, af[mt][1].x, af[mt][0].y, af[mt][1].y,
                             bf[j].x, bf[j].y);
#pragma unroll
            for (int j = 0; j < 8; ++j)
                bf[j] = *(const uint2*)(Bl + (j * 8 + g) * 32 + tig * 8);
#pragma unroll
            for (int mt = 0; mt < 2; ++mt)
#pragma unroll
                for (int j = 0; j < 8; ++j)
                    mma_tf32(acc[mt][j], af[mt][0].x, af[mt][1].x, af[mt][0].y, af[mt][1].y,
                             bf[j].x, bf[j].y);
#pragma unroll
            for (int mt = 0; mt < 2; ++mt) {
                int tA = wTok + mt * 16 + g;
                af[mt][0] = *(const uint2*)(Al + aoff(tA, tig));
                af[mt][1] = *(const uint2*)(Al + aoff(tA + 8, tig));
            }
#pragma unroll
            for (int j = 0; j < 8; ++j)
                bf[j] = *(const uint2*)(Bh + (j * 8 + g) * 32 + tig * 8);
#pragma unroll
            for (int mt = 0; mt < 2; ++mt)
#pragma unroll
                for (int j = 0; j < 8; ++j)
                    mma_tf32(acc[mt][j], af[mt][0].x, af[mt][1].x, af[mt][0].y, af[mt][1].y,
                             bf[j].x, bf[j].y);
        }

        if (more) STORE_CHUNK(buf ^ 1);
        __syncthreads();
    }

    // ---- epilogue: K-split reduction into L[128][65] ----
    float* L = (float*)db;
    if (set == 0) {
#pragma unroll
        for (int mt = 0; mt < 2; ++mt)
#pragma unroll
            for (int j = 0; j < 8; ++j) {
                int r = wTok + mt * 16 + g, cb = j * 8 + tig * 2;
                L[r * 65 + cb]           = acc[mt][j][0];
                L[r * 65 + cb + 1]       = acc[mt][j][1];
                L[(r + 8) * 65 + cb]     = acc[mt][j][2];
                L[(r + 8) * 65 + cb + 1] = acc[mt][j][3];
            }
    }
    __syncthreads();
    if (set == 1) {
#pragma unroll
        for (int mt = 0; mt < 2; ++mt)
#pragma unroll
            for (int j = 0; j < 8; ++j) {
                int r = wTok + mt * 16 + g, cb = j * 8 + tig * 2;
                L[r * 65 + cb]           += acc[mt][j][0];
                L[r * 65 + cb + 1]       += acc[mt][j][1];
                L[(r + 8) * 65 + cb]     += acc[mt][j][2];
                L[(r + 8) * 65 + cb + 1] += acc[mt][j][3];
            }
    }
    __syncthreads();

    float* gL = out + OFF_LOGITS + (size_t)tok0 * NEXP;
    for (int idx = tid; idx < MT * NEXP; idx += THREADS)
        gL[idx] = L[(idx >> 6) * 65 + (idx & 63)];
    __syncthreads();

    if (tid < MT) {
        float* row = L + tid * 65;
        float mx = row[0];
#pragma unroll 8
        for (int e = 1; e < NEXP; ++e) mx = fmaxf(mx, row[e]);
        float s = 0.0f;
#pragma unroll 8
        for (int e = 0; e < NEXP; ++e) s += expf(row[e] - mx);
        float inv = 1.0f / s;
#pragma unroll 8
        for (int e = 0; e < NEXP; ++e) row[e] = expf(row[e] - mx) * inv;
    }
    __syncthreads();

    float* gS = out + OFF_SCORES + (size_t)tok0 * NEXP;
    for (int idx = tid; idx < MT * NEXP; idx += THREADS)
        gS[idx] = L[(idx >> 6) * 65 + (idx & 63)];

    // top-12 (biased ranking; strict > keeps lowest index on ties); write top-8,
    // flag near-tie tokens for exact-fp32 repair.
    if (tid < MT) {
        const float* rp = L + tid * 65;
        float bv[NCAND];
        int   bix[NCAND];
        u64 mask = 0ull;
#pragma unroll
        for (int k = 0; k < NCAND; ++k) {
            float best = -1e30f;
            int bi = 0;
            for (int e = 0; e < NEXP; ++e) {
                if (!((mask >> e) & 1ull)) {
                    float v = rp[e] + s_bias[e];
                    if (v > best) { best = v; bi = e; }
                }
            }
            mask |= 1ull << bi;
            bv[k] = best;
            bix[k] = bi;
        }
        float w[TOPK], ss = 0.0f;
#pragma unroll
        for (int k = 0; k < TOPK; ++k) { w[k] = rp[bix[k]]; ss += w[k] * w[k]; }
        float winv = 1.0f / sqrtf(ss);

        const int tok = tok0 + tid;
        float* gW = out + OFF_W   + (size_t)tok * TOPK;
        float* gI = out + OFF_IDX + (size_t)tok * TOPK;
#pragma unroll
        for (int k = 0; k < TOPK; ++k) {
            gW[k] = w[k] * winv;
            gI[k] = (float)bix[k];
        }

        float ming = bv[0] - bv[1];
#pragma unroll
        for (int j = 1; j < 8; ++j) ming = fminf(ming, bv[j] - bv[j + 1]);
        if (ming < THRESH) {
            int pos = atomicAdd(&g_nflag, 1);
            g_list[pos] = tok;
#pragma unroll
            for (int j = 0; j < NCAND; ++j) g_cand[tok * NCAND + j] = bix[j];
        }
    }
}

// Repair: recompute the 12 candidate logits in exact fp32 for flagged tokens,
// re-rank, rewrite indices + weights (weights gathered from MMA scores row).
__global__ void __launch_bounds__(384, 2)
repair_kernel(const float* __restrict__ x, const float* __restrict__ sbias_g,
              const float* __restrict__ noise, float* __restrict__ out) {
    __shared__ float sxj[DIM];
    __shared__ float sl[NCAND];
    __shared__ int   se[NCAND];

    const int tid  = threadIdx.x;
    const int wid  = tid >> 5;
    const int lane = tid & 31;
    const int n    = g_nflag;

    for (int i = blockIdx.x; i < n; i += gridDim.x) {
        const int tok = g_list[i];
        __syncthreads();   // protect smem reuse across iterations

        const float* xr = x     + (size_t)tok * DIM;
        const float* nr = noise + (size_t)tok * DIM;
        for (int idx = tid; idx < DIM; idx += 384)
            sxj[idx] = xr[idx] * (0.99f + nr[idx] * 0.02f);
        __syncthreads();

        if (wid < NCAND) {
            const int e = g_cand[tok * NCAND + wid];
            const float* wt = g_WT + (size_t)e * DIM;
            float a = 0.0f;
            for (int k = lane; k < DIM; k += 32 * 4) {
                a += sxj[k]            * wt[k];
                a += sxj[k + 32]       * wt[k + 32];
                a += sxj[k + 64]       * wt[k + 64];
                a += sxj[k + 96]       * wt[k + 96];
            }
#pragma unroll
            for (int o = 16; o; o >>= 1) a += __shfl_xor_sync(0xFFFFFFFFu, a, o);
            if (lane == 0) { sl[wid] = a; se[wid] = e; }
        }
        __syncthreads();

        if (tid == 0) {
            float mxl = sl[0];
#pragma unroll
            for (int j = 1; j < NCAND; ++j) mxl = fmaxf(mxl, sl[j]);
            // scale so candidate scores match the MMA score row's normalization
            float s0 = out[OFF_SCORES + (size_t)tok * NEXP + se[0]];
            float C = s0 / expf(sl[0] - mxl);
            float bval[NCAND];
#pragma unroll
            for (int j = 0; j < NCAND; ++j)
                bval[j] = expf(sl[j] - mxl) * C + sbias_g[se[j]];

            int ix[TOPK];
            unsigned m2 = 0;
#pragma unroll
            for (int k = 0; k < TOPK; ++k) {
                float best = -1e30f;
                int bj = 0, beste = NEXP;
                for (int j = 0; j < NCAND; ++j) {
                    if (!((m2 >> j) & 1u)) {
                        float v = bval[j];
                        int e = se[j];
                        if (v > best || (v == best && e < beste)) {
                            best = v; bj = j; beste = e;
                        }
                    }
                }
                m2 |= 1u << bj;
                ix[k] = se[bj];
            }
            float w[TOPK], ss = 0.0f;
#pragma unroll
            for (int k = 0; k < TOPK; ++k) {
                w[k] = out[OFF_SCORES + (size_t)tok * NEXP + ix[k]];
                ss += w[k] * w[k];
            }
            float winv = 1.0f / sqrtf(ss);
            float* gW = out + OFF_W   + (size_t)tok * TOPK;
            float* gI = out + OFF_IDX + (size_t)tok * TOPK;
#pragma unroll
            for (int k = 0; k < TOPK; ++k) {
                gW[k] = w[k] * winv;
                gI[k] = (float)ix[k];
            }
        }
    }
}

__global__ void bincount_kernel(const float* __restrict__ gI, float* __restrict__ cnt) {
    __shared__ int h[NEXP];
    const int tid = threadIdx.x;
    if (tid < NEXP) h[tid] = 0;
    __syncthreads();
    for (int idx = blockIdx.x * blockDim.x + tid; idx < N_TOK * TOPK;
         idx += gridDim.x * blockDim.x)
        atomicAdd(&h[(int)gI[idx]], 1);
    __syncthreads();
    if (tid < NEXP && h[tid]) atomicAdd(&cnt[tid], (float)h[tid]);
}

extern "C" void kernel_launch(void* const* d_in, const int* in_sizes, int n_in,
                              void* d_out, int out_size) {
    const float* x     = (const float*)d_in[0];
    const float* W     = (const float*)d_in[1];
    const float* sbias = (const float*)d_in[2];
    const float* noise = (const float*)d_in[3];
    float* out = (float*)d_out;

    cudaFuncSetAttribute(router_kernel, cudaFuncAttributeMaxDynamicSharedMemorySize,
                         SMEM_BYTES);

    zero_cnt_kernel<<<1, NEXP>>>(out + OFF_CNT);
    prep_W_kernel<<<(NK8 * NEXP * 4) / 256, 256>>>(W);
    router_kernel<<<NBLK, THREADS, SMEM_BYTES>>>(x, sbias, noise, out);
    repair_kernel<<<256, 384>>>(x, sbias, noise, out);
    bincount_kernel<<<64, 256>>>(out + OFF_IDX, out + OFF_CNT);
}

// round 6
// speedup vs baseline: 1.3435x; 1.3255x over previous
#include <cuda_runtime.h>
#include <cuda_bf16.h>
#include <cstdint>

// MoE router: jitter -> GEMM (16384x4096 @ 4096x64) -> softmax -> biased top-8
// -> L2-norm weights -> bincount.  GEMM via legacy mma.sync.m16n8k16.bf16
// (sm_103 base target), 3xBF16 split (hi+lo = 16 mantissa bits, dropped lo*lo
// term ~2^-18 relative).  Near-tie tokens repaired in exact fp32.

#define N_TOK   16384
#define DIM     4096
#define NEXP    64
#define TOPK    8
#define NCAND   12
#define MT      128
#define KC      32              // K per chunk = 16 kp words = 2 k16-steps
#define NCHUNK  (DIM / KC)      // 128
#define THREADS 256
#define NBLK    (N_TOK / MT)    // 128
#define THRESH  2e-5f

#define OFF_LOGITS 0
#define OFF_SCORES (N_TOK * NEXP)
#define OFF_W      (2 * N_TOK * NEXP)
#define OFF_IDX    (2 * N_TOK * NEXP + N_TOK * TOPK)
#define OFF_CNT    (2 * N_TOK * NEXP + 2 * N_TOK * TOPK)

// dynamic smem (u32 words), per buf 24576 B:
//   A_hi [16 kp][128 tok] u32  : 8192 B
//   A_lo                        : 8192 B
//   B_hi [16 kp][64 e]   u32   : 4096 B
//   B_lo                        : 4096 B
#define AHIB(b) ((b) * 24576)
#define ALOB(b) ((b) * 24576 + 8192)
#define BHIB(b) ((b) * 24576 + 16384)
#define BLOB(b) ((b) * 24576 + 20480)
#define SMEM_BYTES 49152

typedef unsigned long long u64;

// XOR'ed word index within an A plane / B plane (bank-conflict-free both sides)
#define AW(kp, tok) ((kp) * 128 + ((tok) ^ (((kp) & 3) << 3)))
#define BW(kp, e)   ((kp) * 64  + ((e)   ^ (((kp) & 3) << 3)))

__device__ uint32_t g_Bh[NCHUNK * 16 * NEXP];   // [chunk][kp][e^xor] packed bf16x2
__device__ uint32_t g_Bl[NCHUNK * 16 * NEXP];
__device__ float g_WT[NEXP * DIM];              // [e][k] fp32 for repair
__device__ int g_nflag;
__device__ int g_list[N_TOK];
__device__ int g_cand[N_TOK * NCAND];

__device__ __forceinline__ uint32_t pack_bf16x2(float hi_elem, float lo_elem) {
    // d.hi = bf16(hi_elem), d.lo = bf16(lo_elem)
    uint32_t d;
    asm("cvt.rn.bf16x2.f32 %0, %1, %2;" : "=r"(d) : "f"(hi_elem), "f"(lo_elem));
    return d;
}

__device__ __forceinline__ void mma_bf16(float* c,
                                         uint32_t a0, uint32_t a1, uint32_t a2, uint32_t a3,
                                         uint32_t b0, uint32_t b1) {
    asm volatile(
        "mma.sync.aligned.m16n8k16.row.col.f32.bf16.bf16.f32 "
        "{%0,%1,%2,%3}, {%4,%5,%6,%7}, {%8,%9}, {%0,%1,%2,%3};"
        : "+f"(c[0]), "+f"(c[1]), "+f"(c[2]), "+f"(c[3])
        : "r"(a0), "r"(a1), "r"(a2), "r"(a3), "r"(b0), "r"(b1));
}

__global__ void zero_cnt_kernel(float* g) {
    g[threadIdx.x] = 0.0f;
    if (threadIdx.x == 0) g_nflag = 0;
}

__global__ void prep_W_kernel(const float* __restrict__ W) {
    int p = blockIdx.x * 256 + threadIdx.x;       // 131072
    int e     = p & 63;
    int kp    = (p >> 6) & 15;
    int chunk = p >> 10;
    int k = chunk * KC + 2 * kp;
    float w0 = W[(size_t)k * NEXP + e];
    float w1 = W[(size_t)(k + 1) * NEXP + e];
    uint32_t h = pack_bf16x2(w1, w0);
    float r0 = w0 - __uint_as_float(h << 16);
    float r1 = w1 - __uint_as_float(h & 0xFFFF0000u);
    uint32_t l = pack_bf16x2(r1, r0);
    int idx = chunk * 1024 + BW(kp, e);
    g_Bh[idx] = h;
    g_Bl[idx] = l;
    g_WT[(size_t)e * DIM + k]     = w0;
    g_WT[(size_t)e * DIM + k + 1] = w1;
}

__global__ void __launch_bounds__(THREADS, 1)
router_kernel(const float* __restrict__ x, const float* __restrict__ sbias_g,
              const float* __restrict__ noise, float* __restrict__ out) {
    extern __shared__ char db[];
    __shared__ float s_bias[NEXP];

    const int tid  = threadIdx.x;
    const int wid  = tid >> 5;
    const int lane = tid & 31;
    const int g    = lane >> 2;
    const int tig  = lane & 3;
    const int set  = wid >> 2;               // K-split half (k16 step within chunk)
    const int wTok = (wid & 3) * 32;
    const int tok0 = blockIdx.x * MT;

    if (tid < NEXP) s_bias[tid] = sbias_g[tid];

    // staging: thread -> (token, k-half of 16 elems = 8 kp)
    const int t_tok  = tid & 127;
    const int t_half = tid >> 7;
    const float* xg = x     + (size_t)(tok0 + t_tok) * DIM + t_half * 16;
    const float* ng = noise + (size_t)(tok0 + t_tok) * DIM + t_half * 16;
    const uint4* pBh4 = (const uint4*)g_Bh;   // 256 uint4 per chunk
    const uint4* pBl4 = (const uint4*)g_Bl;

    float acc[2][8][4];
#pragma unroll
    for (int mt = 0; mt < 2; ++mt)
#pragma unroll
        for (int j = 0; j < 8; ++j)
#pragma unroll
            for (int q = 0; q < 4; ++q) acc[mt][j][q] = 0.0f;

    float4 rx[4], rn[4];
    uint4  rbh, rbl;

#pragma unroll
    for (int j = 0; j < 4; ++j) {
        rx[j] = *(const float4*)(xg + 4 * j);
        rn[j] = *(const float4*)(ng + 4 * j);
    }
    rbh = pBh4[tid];
    rbl = pBl4[tid];

#define STORE_CHUNK(BUF) do {                                                   \
        uint32_t* Ah = (uint32_t*)(db + AHIB(BUF));                             \
        uint32_t* Al = (uint32_t*)(db + ALOB(BUF));                             \
        _Pragma("unroll")                                                       \
        for (int j = 0; j < 4; ++j) {                                           \
            float v0 = rx[j].x * (0.99f + rn[j].x * 0.02f);                     \
            float v1 = rx[j].y * (0.99f + rn[j].y * 0.02f);                     \
            float v2 = rx[j].z * (0.99f + rn[j].z * 0.02f);                     \
            float v3 = rx[j].w * (0.99f + rn[j].w * 0.02f);                     \
            uint32_t h0 = pack_bf16x2(v1, v0);                                  \
            uint32_t h1 = pack_bf16x2(v3, v2);                                  \
            float r0 = v0 - __uint_as_float(h0 << 16);                          \
            float r1 = v1 - __uint_as_float(h0 & 0xFFFF0000u);                  \
            float r2 = v2 - __uint_as_float(h1 << 16);                          \
            float r3 = v3 - __uint_as_float(h1 & 0xFFFF0000u);                  \
            uint32_t l0 = pack_bf16x2(r1, r0);                                  \
            uint32_t l1 = pack_bf16x2(r3, r2);                                  \
            int kp0 = t_half * 8 + 2 * j;                                       \
            Ah[AW(kp0, t_tok)]     = h0;                                        \
            Ah[AW(kp0 + 1, t_tok)] = h1;                                        \
            Al[AW(kp0, t_tok)]     = l0;                                        \
            Al[AW(kp0 + 1, t_tok)] = l1;                                        \
        }                                                                       \
        ((uint4*)(db + BHIB(BUF)))[tid] = rbh;                                  \
        ((uint4*)(db + BLOB(BUF)))[tid] = rbl;                                  \
    } while (0)

    STORE_CHUNK(0);
    __syncthreads();

#pragma unroll 1
    for (int c = 0; c < NCHUNK; ++c) {
        const int buf = c & 1;
        const bool more = (c + 1 < NCHUNK);

        if (more) {
            const int cb = (c + 1) * KC;
#pragma unroll
            for (int j = 0; j < 4; ++j) {
                rx[j] = *(const float4*)(xg + cb + 4 * j);
                rn[j] = *(const float4*)(ng + cb + 4 * j);
            }
            rbh = pBh4[(c + 1) * 256 + tid];
            rbl = pBl4[(c + 1) * 256 + tid];
        }

        // ---- my k16 step of this chunk: kp in [set*8, set*8+8) ----
        {
            const uint32_t* Ah = (const uint32_t*)(db + AHIB(buf));
            const uint32_t* Al = (const uint32_t*)(db + ALOB(buf));
            const uint32_t* Bh = (const uint32_t*)(db + BHIB(buf));
            const uint32_t* Bl = (const uint32_t*)(db + BLOB(buf));
            const int kb = set * 8;

            uint32_t ah[2][4], al[2][4], bh[8][2], bl[8][2];
#pragma unroll
            for (int mt = 0; mt < 2; ++mt) {
                int tr = wTok + mt * 16 + g;
                ah[mt][0] = Ah[AW(kb + tig, tr)];
                ah[mt][1] = Ah[AW(kb + tig, tr + 8)];
                ah[mt][2] = Ah[AW(kb + tig + 4, tr)];
                ah[mt][3] = Ah[AW(kb + tig + 4, tr + 8)];
            }
#pragma unroll
            for (int j = 0; j < 8; ++j) {
                bh[j][0] = Bh[BW(kb + tig, j * 8 + g)];
                bh[j][1] = Bh[BW(kb + tig + 4, j * 8 + g)];
            }
            // a_hi * b_hi
#pragma unroll
            for (int mt = 0; mt < 2; ++mt)
#pragma unroll
                for (int j = 0; j < 8; ++j)
                    mma_bf16(acc[mt][j], ah[mt][0], ah[mt][1], ah[mt][2], ah[mt][3],
                             bh[j][0], bh[j][1]);
            // a_hi * b_lo
#pragma unroll
            for (int j = 0; j < 8; ++j) {
                bl[j][0] = Bl[BW(kb + tig, j * 8 + g)];
                bl[j][1] = Bl[BW(kb + tig + 4, j * 8 + g)];
            }
#pragma unroll
            for (int mt = 0; mt < 2; ++mt)
#pragma unroll
                for (int j = 0; j < 8; ++j)
                    mma_bf16(acc[mt][j], ah[mt][0], ah[mt][1], ah[mt][2], ah[mt][3],
                             bl[j][0], bl[j][1]);
            // a_lo * b_hi
#pragma unroll
            for (int mt = 0; mt < 2; ++mt) {
                int tr = wTok + mt * 16 + g;
                al[mt][0] = Al[AW(kb + tig, tr)];
                al[mt][1] = Al[AW(kb + tig, tr + 8)];
                al[mt][2] = Al[AW(kb + tig + 4, tr)];
                al[mt][3] = Al[AW(kb + tig + 4, tr + 8)];
            }
#pragma unroll
            for (int mt = 0; mt < 2; ++mt)
#pragma unroll
                for (int j = 0; j < 8; ++j)
                    mma_bf16(acc[mt][j], al[mt][0], al[mt][1], al[mt][2], al[mt][3],
                             bh[j][0], bh[j][1]);
        }

        if (more) STORE_CHUNK(buf ^ 1);
        __syncthreads();
    }

    // ---- epilogue: K-split reduction into L[128][65] ----
    float* L = (float*)db;
    if (set == 0) {
#pragma unroll
        for (int mt = 0; mt < 2; ++mt)
#pragma unroll
            for (int j = 0; j < 8; ++j) {
                int r = wTok + mt * 16 + g, cb = j * 8 + tig * 2;
                L[r * 65 + cb]           = acc[mt][j][0];
                L[r * 65 + cb + 1]       = acc[mt][j][1];
                L[(r + 8) * 65 + cb]     = acc[mt][j][2];
                L[(r + 8) * 65 + cb + 1] = acc[mt][j][3];
            }
    }
    __syncthreads();
    if (set == 1) {
#pragma unroll
        for (int mt = 0; mt < 2; ++mt)
#pragma unroll
            for (int j = 0; j < 8; ++j) {
                int r = wTok + mt * 16 + g, cb = j * 8 + tig * 2;
                L[r * 65 + cb]           += acc[mt][j][0];
                L[r * 65 + cb + 1]       += acc[mt][j][1];
                L[(r + 8) * 65 + cb]     += acc[mt][j][2];
                L[(r + 8) * 65 + cb + 1] += acc[mt][j][3];
            }
    }
    __syncthreads();

    float* gL = out + OFF_LOGITS + (size_t)tok0 * NEXP;
    for (int idx = tid; idx < MT * NEXP; idx += THREADS)
        gL[idx] = L[(idx >> 6) * 65 + (idx & 63)];
    __syncthreads();

    if (tid < MT) {
        float* row = L + tid * 65;
        float mx = row[0];
#pragma unroll 8
        for (int e = 1; e < NEXP; ++e) mx = fmaxf(mx, row[e]);
        float s = 0.0f;
#pragma unroll 8
        for (int e = 0; e < NEXP; ++e) s += expf(row[e] - mx);
        float inv = 1.0f / s;
#pragma unroll 8
        for (int e = 0; e < NEXP; ++e) row[e] = expf(row[e] - mx) * inv;
    }
    __syncthreads();

    float* gS = out + OFF_SCORES + (size_t)tok0 * NEXP;
    for (int idx = tid; idx < MT * NEXP; idx += THREADS)
        gS[idx] = L[(idx >> 6) * 65 + (idx & 63)];

    // top-12 biased ranking; write top-8; flag near-ties for exact-fp32 repair
    if (tid < MT) {
        const float* rp = L + tid * 65;
        float bv[NCAND];
        int   bix[NCAND];
        u64 mask = 0ull;
#pragma unroll
        for (int k = 0; k < NCAND; ++k) {
            float best = -1e30f;
            int bi = 0;
            for (int e = 0; e < NEXP; ++e) {
                if (!((mask >> e) & 1ull)) {
                    float v = rp[e] + s_bias[e];
                    if (v > best) { best = v; bi = e; }
                }
            }
            mask |= 1ull << bi;
            bv[k] = best;
            bix[k] = bi;
        }
        float w[TOPK], ss = 0.0f;
#pragma unroll
        for (int k = 0; k < TOPK; ++k) { w[k] = rp[bix[k]]; ss += w[k] * w[k]; }
        float winv = 1.0f / sqrtf(ss);

        const int tok = tok0 + tid;
        float* gW = out + OFF_W   + (size_t)tok * TOPK;
        float* gI = out + OFF_IDX + (size_t)tok * TOPK;
#pragma unroll
        for (int k = 0; k < TOPK; ++k) {
            gW[k] = w[k] * winv;
            gI[k] = (float)bix[k];
        }

        float ming = bv[0] - bv[1];
#pragma unroll
        for (int j = 1; j < 8; ++j) ming = fminf(ming, bv[j] - bv[j + 1]);
        if (ming < THRESH) {
            int pos = atomicAdd(&g_nflag, 1);
            g_list[pos] = tok;
#pragma unroll
            for (int j = 0; j < NCAND; ++j) g_cand[tok * NCAND + j] = bix[j];
        }
    }
}

// Repair: recompute 12 candidate logits in exact fp32 for flagged tokens,
// re-rank, rewrite indices + weights (weights gathered from MMA scores row).
__global__ void __launch_bounds__(384, 2)
repair_kernel(const float* __restrict__ x, const float* __restrict__ sbias_g,
              const float* __restrict__ noise, float* __restrict__ out) {
    __shared__ float sxj[DIM];
    __shared__ float sl[NCAND];
    __shared__ int   se[NCAND];

    const int tid  = threadIdx.x;
    const int wid  = tid >> 5;
    const int lane = tid & 31;
    const int n    = g_nflag;

    for (int i = blockIdx.x; i < n; i += gridDim.x) {
        const int tok = g_list[i];
        __syncthreads();

        const float* xr = x     + (size_t)tok * DIM;
        const float* nr = noise + (size_t)tok * DIM;
        for (int idx = tid; idx < DIM; idx += 384)
            sxj[idx] = xr[idx] * (0.99f + nr[idx] * 0.02f);
        __syncthreads();

        if (wid < NCAND) {
            const int e = g_cand[tok * NCAND + wid];
            const float* wt = g_WT + (size_t)e * DIM;
            float a = 0.0f;
            for (int k = lane; k < DIM; k += 32 * 4) {
                a += sxj[k]       * wt[k];
                a += sxj[k + 32]  * wt[k + 32];
                a += sxj[k + 64]  * wt[k + 64];
                a += sxj[k + 96]  * wt[k + 96];
            }
#pragma unroll
            for (int o = 16; o; o >>= 1) a += __shfl_xor_sync(0xFFFFFFFFu, a, o);
            if (lane == 0) { sl[wid] = a; se[wid] = e; }
        }
        __syncthreads();

        if (tid == 0) {
            float mxl = sl[0];
#pragma unroll
            for (int j = 1; j < NCAND; ++j) mxl = fmaxf(mxl, sl[j]);
            float s0 = out[OFF_SCORES + (size_t)tok * NEXP + se[0]];
            float C = s0 / expf(sl[0] - mxl);
            float bval[NCAND];
#pragma unroll
            for (int j = 0; j < NCAND; ++j)
                bval[j] = expf(sl[j] - mxl) * C + sbias_g[se[j]];

            int ix[TOPK];
            unsigned m2 = 0;
#pragma unroll
            for (int k = 0; k < TOPK; ++k) {
                float best = -1e30f;
                int bj = 0, beste = NEXP;
                for (int j = 0; j < NCAND; ++j) {
                    if (!((m2 >> j) & 1u)) {
                        float v = bval[j];
                        int e = se[j];
                        if (v > best || (v == best && e < beste)) {
                            best = v; bj = j; beste = e;
                        }
                    }
                }
                m2 |= 1u << bj;
                ix[k] = se[bj];
            }
            float w[TOPK], ss = 0.0f;
#pragma unroll
            for (int k = 0; k < TOPK; ++k) {
                w[k] = out[OFF_SCORES + (size_t)tok * NEXP + ix[k]];
                ss += w[k] * w[k];
            }
            float winv = 1.0f / sqrtf(ss);
            float* gW = out + OFF_W   + (size_t)tok * TOPK;
            float* gI = out + OFF_IDX + (size_t)tok * TOPK;
#pragma unroll
            for (int k = 0; k < TOPK; ++k) {
                gW[k] = w[k] * winv;
                gI[k] = (float)ix[k];
            }
        }
    }
}

__global__ void bincount_kernel(const float* __restrict__ gI, float* __restrict__ cnt) {
    __shared__ int h[NEXP];
    const int tid = threadIdx.x;
    if (tid < NEXP) h[tid] = 0;
    __syncthreads();
    for (int idx = blockIdx.x * blockDim.x + tid; idx < N_TOK * TOPK;
         idx += gridDim.x * blockDim.x)
        atomicAdd(&h[(int)gI[idx]], 1);
    __syncthreads();
    if (tid < NEXP && h[tid]) atomicAdd(&cnt[tid], (float)h[tid]);
}

extern "C" void kernel_launch(void* const* d_in, const int* in_sizes, int n_in,
                              void* d_out, int out_size) {
    const float* x     = (const float*)d_in[0];
    const float* W     = (const float*)d_in[1];
    const float* sbias = (const float*)d_in[2];
    const float* noise = (const float*)d_in[3];
    float* out = (float*)d_out;

    cudaFuncSetAttribute(router_kernel, cudaFuncAttributeMaxDynamicSharedMemorySize,
                         SMEM_BYTES);

    zero_cnt_kernel<<<1, NEXP>>>(out + OFF_CNT);
    prep_W_kernel<<<(NCHUNK * 16 * NEXP) / 256, 256>>>(W);
    router_kernel<<<NBLK, THREADS, SMEM_BYTES>>>(x, sbias, noise, out);
    repair_kernel<<<256, 384>>>(x, sbias, noise, out);
    bincount_kernel<<<64, 256>>>(out + OFF_IDX, out + OFF_CNT);
}